// round 10
// baseline (speedup 1.0000x reference)
#include <cuda_runtime.h>

// SpatialWeightsEsDot on GB300.
//   phi = w_phi @ u (1x1 conv), layout [b][c][y][x]
//   M_{dy,dx}[b][y][x] = sum_c phi[b,c,y,x]*phi[b,c,y+dy,x+dx]  (zero outside image)
//   score[p,d] = 1[p+d in image] * sum_{e in 3x3} M_d[p+e]
//   out = softmax over the 49 offsets -> [2,128,128,1,49]

#define HH 128
#define WW 128
#define CC 64

__device__ float g_phi[2 * CC * HH * WW];     // [b][c][y][x]
__device__ float g_M[49 * 2 * HH * WW];       // [off][b][y][x], off=(dy+3)*7+(dx+3)

typedef unsigned long long u64;

__device__ __forceinline__ void ffma2(u64& d, u64 a, u64 b) {
    asm("fma.rn.f32x2 %0, %1, %2, %3;" : "=l"(d) : "l"(a), "l"(b), "l"(d));
}
__device__ __forceinline__ u64 dup2(float v) {
    u64 d; asm("mov.b64 %0, {%1, %1};" : "=l"(d) : "f"(v)); return d;
}

// ---------------------------------------------------------------------------
// K1: phi v5. Thread = 4 px x 4 outputs. Per k-step: 1 LDG.128 (u) +
// 2 broadcast LDS.128 (pre-duplicated {w,w} pairs) + 8 FFMA2 = 11 instr per
// 32 lane-FMAs. grid (256 px-blocks, 2 og-halves) x 256 thr = 4096 warps
// (27.7/SM) -- removes the 13.8-warp/SM grid ceiling of all prior variants.
// Warp = og-group (4 outputs); all 8 warps of a block share u lines via L1.
// ---------------------------------------------------------------------------
__global__ void __launch_bounds__(256)
phi_kernel(const float* __restrict__ u, const float* __restrict__ w) {
    __shared__ u64 s_w2[CC * CC];              // [k][o] duplicated {w,w}, 32KB
    int tid = threadIdx.x;
    for (int i = tid; i < CC * CC; i += 256) {
        int k = i >> 6, o = i & 63;
        s_w2[i] = dup2(w[o * CC + k]);
    }
    __syncthreads();

    int lane = tid & 31;
    int wrp  = tid >> 5;                       // 0..7
    int o0   = (blockIdx.y * 8 + wrp) * 4;     // 4 outputs per thread
    int pix  = blockIdx.x * 128 + lane * 4;    // 4 consecutive pixels
    int b    = pix >> 14;
    int p    = pix & 16383;

    const float4* ub = (const float4*)(u + (size_t)b * CC * 16384 + p); // +k*4096

    u64 acc[4][2];
#pragma unroll
    for (int j = 0; j < 4; j++) { acc[j][0] = 0ull; acc[j][1] = 0ull; }

#pragma unroll 4
    for (int k = 0; k < CC; k++) {
        longlong2 uv = *(const longlong2*)&ub[(size_t)k * 4096];
        u64 u01 = (u64)uv.x;                   // pixels p, p+1
        u64 u23 = (u64)uv.y;                   // pixels p+2, p+3
        ulonglong2 w01 = *(const ulonglong2*)&s_w2[k * CC + o0];      // {w0,w0},{w1,w1}
        ulonglong2 w23 = *(const ulonglong2*)&s_w2[k * CC + o0 + 2];  // {w2,w2},{w3,w3}
        ffma2(acc[0][0], u01, w01.x); ffma2(acc[0][1], u23, w01.x);
        ffma2(acc[1][0], u01, w01.y); ffma2(acc[1][1], u23, w01.y);
        ffma2(acc[2][0], u01, w23.x); ffma2(acc[2][1], u23, w23.x);
        ffma2(acc[3][0], u01, w23.y); ffma2(acc[3][1], u23, w23.y);
    }

    float* op = g_phi + ((size_t)b * CC + o0) * 16384 + p;
#pragma unroll
    for (int j = 0; j < 4; j++) {
        *(u64*)(op + (size_t)j * 16384)     = acc[j][0];
        *(u64*)(op + (size_t)j * 16384 + 2) = acc[j][1];
    }
}

// ---------------------------------------------------------------------------
// K2: M maps. grid (256 rows, 2 dy-halves), block 128 = 4 warps (dy groups).
// Lane = 4 consecutive pixels. Per channel: 1 center LDG.128 + 3 shifted
// LDG.128 -> 12-float register window serves all 7 dx via shifted FMAs.
// ---------------------------------------------------------------------------
__global__ void __launch_bounds__(128)
m_kernel() {
    int lane = threadIdx.x & 31;
    int grp  = (threadIdx.x >> 5) + blockIdx.y * 4;  // 0..6 -> dy = grp-3
    if (grp >= 7) return;                            // idle 4th warp of half 1
    int row  = blockIdx.x;                           // 0..255
    int b = row >> 7, y = row & 127;
    int dy = grp - 3;
    int x  = lane << 2;
    int ys = y + dy;
    bool rowok = (unsigned)ys < (unsigned)HH;
    bool lok = (x > 0);
    bool rok = (x < WW - 4);

    const float* pcb = g_phi + b * CC * 16384 + y  * WW + x;   // +c*16384
    const float* psb = g_phi + b * CC * 16384 + ys * WW + x;

    float acc[28];
#pragma unroll
    for (int i = 0; i < 28; i++) acc[i] = 0.f;

#pragma unroll 4
    for (int c = 0; c < CC; c++) {
        const float* pc_ = pcb + c * 16384;
        const float* ps_ = psb + c * 16384;
        float4 ctr = *(const float4*)pc_;
        float4 w0 = make_float4(0.f, 0.f, 0.f, 0.f);
        float4 w1 = w0, w2 = w0;
        if (rowok) {
            w1 = *(const float4*)ps_;
            if (lok) w0 = *(const float4*)(ps_ - 4);
            if (rok) w2 = *(const float4*)(ps_ + 4);
        }
        float win[12] = {w0.x, w0.y, w0.z, w0.w,
                         w1.x, w1.y, w1.z, w1.w,
                         w2.x, w2.y, w2.z, w2.w};
        float ct[4] = {ctr.x, ctr.y, ctr.z, ctr.w};
#pragma unroll
        for (int d = 0; d < 7; d++)            // dx = d-3
#pragma unroll
            for (int j = 0; j < 4; j++)
                acc[d * 4 + j] += ct[j] * win[1 + d + j];   // phi_s[x+j+(d-3)]
    }

    float* mb = g_M + b * 16384 + y * WW + x;
#pragma unroll
    for (int d = 0; d < 7; d++)
        *(float4*)(mb + (size_t)(grp * 7 + d) * 32768) =
            make_float4(acc[d * 4], acc[d * 4 + 1], acc[d * 4 + 2], acc[d * 4 + 3]);
}

// ---------------------------------------------------------------------------
// K3: boxsum + mask + softmax. grid (2 xb, 128 y, 2 b), block 512.
// Thread (px 0..63, dyg 0..7; dyg==7 idle in compute). Lanes = consecutive x
// -> coalesced M reads. Cross-dy softmax via tiny smem reduction (pitch 9).
// ---------------------------------------------------------------------------
__global__ void __launch_bounds__(512)
attn_kernel(float* __restrict__ out) {
    __shared__ float s_red[64 * 9];
    int t   = threadIdx.x;
    int px  = t & 63;
    int dyg = t >> 6;                          // 0..7
    int b = blockIdx.z, y = blockIdx.y, x = blockIdx.x * 64 + px;

    float sc[7];
    float lmax = -1e30f;
    if (dyg < 7) {
        int dy = dyg - 3;
#pragma unroll
        for (int d3 = 0; d3 < 7; d3++) {
            int dx = d3 - 3;
            float s = 0.f;
            const float* mb = g_M + (size_t)(dyg * 7 + d3) * 32768 + b * 16384;
#pragma unroll
            for (int ey = -1; ey <= 1; ey++) {
                int yy = y + ey;
                if ((unsigned)yy < (unsigned)HH) {
#pragma unroll
                    for (int ex = -1; ex <= 1; ex++) {
                        int xx = x + ex;
                        if ((unsigned)xx < (unsigned)WW) s += mb[yy * WW + xx];
                    }
                }
            }
            bool valid = ((unsigned)(y + dy) < (unsigned)HH) &&
                         ((unsigned)(x + dx) < (unsigned)WW);
            sc[d3] = valid ? s : 0.f;
            lmax = fmaxf(lmax, sc[d3]);
        }
    }
    s_red[px * 9 + dyg] = lmax;                // dyg==7 writes -1e30 (ignored)
    __syncthreads();

    float gmax = s_red[px * 9 + 0];
#pragma unroll
    for (int j = 1; j < 7; j++) gmax = fmaxf(gmax, s_red[px * 9 + j]);

    float e[7];
    float lsum = 0.f;
    if (dyg < 7) {
#pragma unroll
        for (int d3 = 0; d3 < 7; d3++) { e[d3] = __expf(sc[d3] - gmax); lsum += e[d3]; }
    }
    __syncthreads();                           // protect s_red before overwrite
    s_red[px * 9 + dyg] = lsum;                // dyg==7 writes 0 (lsum init, not read)
    __syncthreads();

    float gsum = 0.f;
#pragma unroll
    for (int j = 0; j < 7; j++) gsum += s_red[px * 9 + j];

    if (dyg < 7) {
        float inv = 1.0f / gsum;
        float* op = out + (size_t)(b * 16384 + y * WW + x) * 49 + dyg * 7;
#pragma unroll
        for (int d3 = 0; d3 < 7; d3++) op[d3] = e[d3] * inv;
    }
}

extern "C" void kernel_launch(void* const* d_in, const int* in_sizes, int n_in,
                              void* d_out, int out_size) {
    const float* u = (const float*)d_in[0];    // [2,64,128,128]
    const float* w = (const float*)d_in[1];    // [64,64]
    float* out = (float*)d_out;                // [2,128,128,1,49]

    phi_kernel<<<dim3(256, 2), 256>>>(u, w);
    m_kernel<<<dim3(256, 2), 128>>>();
    attn_kernel<<<dim3(2, 128, 2), 512>>>(out);
}

// round 12
// speedup vs baseline: 1.4434x; 1.4434x over previous
#include <cuda_runtime.h>

// SpatialWeightsEsDot on GB300.
//   phi = w_phi @ u (1x1 conv), layout [b][c][y][x]
//   M_{dy,dx}[b][y][x] = sum_c phi[b,c,y,x]*phi[b,c,y+dy,x+dx]  (zero outside image)
//   score[p,d] = 1[p+d in image] * sum_{e in 3x3} M_d[p+e]
//   out = softmax over the 49 offsets -> [2,128,128,1,49]

#define HH 128
#define WW 128
#define CC 64

__device__ float g_phi[2 * CC * HH * WW];     // [b][c][y][x]
__device__ float g_M[49 * 2 * HH * WW];       // [off][b][y][x], off=(dy+3)*7+(dx+3)

typedef unsigned long long u64;

__device__ __forceinline__ void ffma2(u64& d, u64 a, u64 b) {
    asm("fma.rn.f32x2 %0, %1, %2, %3;" : "=l"(d) : "l"(a), "l"(b), "l"(d));
}
__device__ __forceinline__ u64 dup2(float v) {
    u64 d; asm("mov.b64 %0, {%1, %1};" : "=l"(d) : "f"(v)); return d;
}

// ---------------------------------------------------------------------------
// K1: phi v6, smem-staged SGEMM. Block = 64 px x 64 outs, 128 thr.
// u tile (64k x 64px) staged to smem ONCE; k-loop reads smem only (no LDG
// latency chain -- the binder in all prior variants). Thread = 16 outs x 2 px:
// per k: 1 LDS.64 (u) + 8 broadcast LDS.128 (pre-dup {w,w}) + 16 FFMA2.
// ---------------------------------------------------------------------------
__global__ void __launch_bounds__(128)
phi_kernel(const float* __restrict__ u, const float* __restrict__ w) {
    __shared__ float s_u[CC * 64];             // [k][px] 16KB
    __shared__ u64 s_w2[CC * CC];              // [k][o] duplicated pairs 32KB
    int tid = threadIdx.x;
    int b   = blockIdx.x >> 8;                 // 256 px-blocks per image
    int p0  = (blockIdx.x << 6) & 16383;

    for (int i = tid; i < CC * CC; i += 128) {
        int k = i >> 6, o = i & 63;
        s_w2[i] = dup2(w[o * CC + k]);
    }
    const float* ub = u + (size_t)b * CC * 16384 + p0;
    for (int i = tid; i < 1024; i += 128) {    // 64k x 16 float4
        int k = i >> 4, p4 = (i & 15) << 2;
        *(float4*)&s_u[k * 64 + p4] = *(const float4*)(ub + (size_t)k * 16384 + p4);
    }
    __syncthreads();

    int lane = tid & 31;
    int o0   = (tid >> 5) << 4;                // warp -> 16 outputs
    int px   = lane << 1;                      // 2 pixels

    u64 acc[16];
#pragma unroll
    for (int j = 0; j < 16; j++) acc[j] = 0ull;

#pragma unroll 4
    for (int k = 0; k < CC; k++) {
        u64 u2 = *(const u64*)&s_u[k * 64 + px];
        const ulonglong2* wp = (const ulonglong2*)&s_w2[k * CC + o0];
#pragma unroll
        for (int m = 0; m < 8; m++) {
            ulonglong2 wv = wp[m];
            ffma2(acc[2 * m],     u2, wv.x);
            ffma2(acc[2 * m + 1], u2, wv.y);
        }
    }

    float* op = g_phi + ((size_t)b * CC + o0) * 16384 + p0 + px;
#pragma unroll
    for (int j = 0; j < 16; j++)
        *(u64*)(op + (size_t)j * 16384) = acc[j];
}

// ---------------------------------------------------------------------------
// K2: M maps v2, smem-staged. grid (256 rows, 2 dy-halves), block 128.
// Per 8-channel chunk: stage 4 phi rows (y-3+rbase .. +3, zeros outside
// image) into smem, then each dy-warp builds its 12-float window from smem
// (29-cyc latency vs ~250-cyc L2) and does 28 FMAs per channel.
// ---------------------------------------------------------------------------
__global__ void __launch_bounds__(128)
m_kernel() {
    __shared__ float s_p[4 * 8 * 128];         // [r][c][px] 16KB
    int tid  = threadIdx.x;
    int lane = tid & 31;
    int wrp  = tid >> 5;                       // 0..3
    int half = blockIdx.y;
    int grp  = wrp + half * 4;                 // 0..7; grp 7 idle in compute
    int row  = blockIdx.x;                     // 0..255
    int b = row >> 7, y = row & 127;
    int rbase = half * 3;                      // half0 rows 0..3, half1 rows 3..6
    int bufC  = 3 - rbase;                     // center (dy=0) buffer row
    int bufW  = grp - rbase;                   // this warp's buffer row
    int x = lane << 2;

    float acc[28];
#pragma unroll
    for (int i = 0; i < 28; i++) acc[i] = 0.f;

    for (int c0 = 0; c0 < CC; c0 += 8) {
        __syncthreads();                       // previous chunk fully consumed
        // stage 4 rows x 8 ch x 128 px = 1024 float4; 8 per thread
        for (int i = tid; i < 1024; i += 128) {
            int r  = i >> 8;
            int c  = (i >> 5) & 7;
            int p4 = (i & 31) << 2;
            int ys = y - 3 + rbase + r;
            float4 v = make_float4(0.f, 0.f, 0.f, 0.f);
            if ((unsigned)ys < (unsigned)HH)
                v = *(const float4*)(g_phi + ((size_t)(b * CC + c0 + c) * HH + ys) * WW + p4);
            *(float4*)&s_p[(r * 8 + c) * 128 + p4] = v;
        }
        __syncthreads();

        if (grp < 7) {
#pragma unroll
            for (int c = 0; c < 8; c++) {
                const float* cr = &s_p[(bufC * 8 + c) * 128];
                const float* sr = &s_p[(bufW * 8 + c) * 128];
                float4 ctr = *(const float4*)(cr + x);
                float4 w0 = make_float4(0.f, 0.f, 0.f, 0.f);
                float4 w2 = w0;
                float4 w1 = *(const float4*)(sr + x);
                if (x > 0)   w0 = *(const float4*)(sr + x - 4);
                if (x < 124) w2 = *(const float4*)(sr + x + 4);
                float win[12] = {w0.x, w0.y, w0.z, w0.w,
                                 w1.x, w1.y, w1.z, w1.w,
                                 w2.x, w2.y, w2.z, w2.w};
                float ct[4] = {ctr.x, ctr.y, ctr.z, ctr.w};
#pragma unroll
                for (int d = 0; d < 7; d++)    // dx = d-3
#pragma unroll
                    for (int j = 0; j < 4; j++)
                        acc[d * 4 + j] += ct[j] * win[1 + d + j];
            }
        }
    }

    if (grp < 7) {
        float* mb = g_M + b * 16384 + y * WW + x;
#pragma unroll
        for (int d = 0; d < 7; d++)
            *(float4*)(mb + (size_t)(grp * 7 + d) * 32768) =
                make_float4(acc[d * 4], acc[d * 4 + 1], acc[d * 4 + 2], acc[d * 4 + 3]);
    }
}

// ---------------------------------------------------------------------------
// K3: boxsum + mask + softmax. grid (2 xb, 128 y, 2 b), block 512.
// Thread (px 0..63, dyg 0..7; dyg==7 idle in compute). Lanes = consecutive x
// -> coalesced M reads. Cross-dy softmax via tiny smem reduction (pitch 9).
// ---------------------------------------------------------------------------
__global__ void __launch_bounds__(512)
attn_kernel(float* __restrict__ out) {
    __shared__ float s_red[64 * 9];
    int t   = threadIdx.x;
    int px  = t & 63;
    int dyg = t >> 6;                          // 0..7
    int b = blockIdx.z, y = blockIdx.y, x = blockIdx.x * 64 + px;

    float sc[7];
    float lmax = -1e30f;
    if (dyg < 7) {
        int dy = dyg - 3;
#pragma unroll
        for (int d3 = 0; d3 < 7; d3++) {
            int dx = d3 - 3;
            float s = 0.f;
            const float* mb = g_M + (size_t)(dyg * 7 + d3) * 32768 + b * 16384;
#pragma unroll
            for (int ey = -1; ey <= 1; ey++) {
                int yy = y + ey;
                if ((unsigned)yy < (unsigned)HH) {
#pragma unroll
                    for (int ex = -1; ex <= 1; ex++) {
                        int xx = x + ex;
                        if ((unsigned)xx < (unsigned)WW) s += mb[yy * WW + xx];
                    }
                }
            }
            bool valid = ((unsigned)(y + dy) < (unsigned)HH) &&
                         ((unsigned)(x + dx) < (unsigned)WW);
            sc[d3] = valid ? s : 0.f;
            lmax = fmaxf(lmax, sc[d3]);
        }
    }
    s_red[px * 9 + dyg] = lmax;                // dyg==7 writes -1e30 (ignored)
    __syncthreads();

    float gmax = s_red[px * 9 + 0];
#pragma unroll
    for (int j = 1; j < 7; j++) gmax = fmaxf(gmax, s_red[px * 9 + j]);

    float e[7];
    float lsum = 0.f;
    if (dyg < 7) {
#pragma unroll
        for (int d3 = 0; d3 < 7; d3++) { e[d3] = __expf(sc[d3] - gmax); lsum += e[d3]; }
    }
    __syncthreads();                           // protect s_red before overwrite
    s_red[px * 9 + dyg] = lsum;                // dyg==7 writes 0 (lsum init, not read)
    __syncthreads();

    float gsum = 0.f;
#pragma unroll
    for (int j = 0; j < 7; j++) gsum += s_red[px * 9 + j];

    if (dyg < 7) {
        float inv = 1.0f / gsum;
        float* op = out + (size_t)(b * 16384 + y * WW + x) * 49 + dyg * 7;
#pragma unroll
        for (int d3 = 0; d3 < 7; d3++) op[d3] = e[d3] * inv;
    }
}

extern "C" void kernel_launch(void* const* d_in, const int* in_sizes, int n_in,
                              void* d_out, int out_size) {
    const float* u = (const float*)d_in[0];    // [2,64,128,128]
    const float* w = (const float*)d_in[1];    // [64,64]
    float* out = (float*)d_out;                // [2,128,128,1,49]

    phi_kernel<<<512, 128>>>(u, w);
    m_kernel<<<dim3(256, 2), 128>>>();
    attn_kernel<<<dim3(2, 128, 2), 512>>>(out);
}

// round 13
// speedup vs baseline: 1.4818x; 1.0266x over previous
#include <cuda_runtime.h>

// SpatialWeightsEsDot on GB300.
//   phi = w_phi @ u (1x1 conv), layout [b][c][y][x]
//   M_{dy,dx}[b][y][x] = sum_c phi[b,c,y,x]*phi[b,c,y+dy,x+dx]  (zero outside image)
//   score[p,d] = 1[p+d in image] * sum_{e in 3x3} M_d[p+e]
//   out = softmax over the 49 offsets -> [2,128,128,1,49]

#define HH 128
#define WW 128
#define CC 64
#define PXT 128                               // pixels per phi block

__device__ float g_phi[2 * CC * HH * WW];     // [b][c][y][x]
__device__ float g_M[49 * 2 * HH * WW];       // [off][b][y][x], off=(dy+3)*7+(dx+3)

typedef unsigned long long u64;

__device__ __forceinline__ void ffma2(u64& d, u64 a, u64 b) {
    asm("fma.rn.f32x2 %0, %1, %2, %3;" : "=l"(d) : "l"(a), "l"(b), "l"(d));
}
__device__ __forceinline__ u64 dup2(float v) {
    u64 d; asm("mov.b64 %0, {%1, %1};" : "=l"(d) : "f"(v)); return d;
}

// ---------------------------------------------------------------------------
// K1: phi v7. Cost model: every LDS.128 pays full 512B/warp on the L1 return
// crossbar (broadcast is NOT free -- round-12 evidence). So minimize smem
// bytes/MAC: thread = 8 px x 4 outs -> per k: 2 LDS.128 (u) + 1 LDS.128
// (w, 4 scalar outs) + 4 dup-movs + 16 FFMA2  (1.5 B/MAC -> ~5.3us crossbar).
// Block 256 thr = 16 pxg x 16 og = 128 px x 64 outs; u+w staged to smem once.
// Grid 256 blocks = 2048 warps (13.8/SM), ~60 regs.
// ---------------------------------------------------------------------------
__global__ void __launch_bounds__(256)
phi_kernel(const float* __restrict__ u, const float* __restrict__ w) {
    __shared__ float s_u[CC * PXT];            // [k][px] 32KB
    __shared__ float s_w[CC * CC];             // [k][o] 16KB
    int tid = threadIdx.x;
    int p0  = blockIdx.x * PXT;                // global pixel base
    int b   = p0 >> 14;
    int pb  = p0 & 16383;

    for (int i = tid; i < CC * CC; i += 256) {
        int k = i >> 6, o = i & 63;
        s_w[i] = w[o * CC + k];
    }
    const float* ub = u + (size_t)b * CC * 16384 + pb;
    for (int i = tid; i < CC * PXT / 4; i += 256) {   // 2048 float4
        int k  = i >> 5;                       // 32 float4 per k-row
        int p4 = (i & 31) << 2;
        *(float4*)&s_u[k * PXT + p4] = *(const float4*)(ub + (size_t)k * 16384 + p4);
    }
    __syncthreads();

    int pxg = tid & 15;                        // 16 groups x 8 px
    int og  = tid >> 4;                        // 16 groups x 4 outs
    int px  = pxg << 3;
    int o0  = og << 2;

    u64 acc[4][4];                             // [out][px-pair]
#pragma unroll
    for (int j = 0; j < 4; j++)
#pragma unroll
        for (int p = 0; p < 4; p++) acc[j][p] = 0ull;

#pragma unroll 4
    for (int k = 0; k < CC; k++) {
        ulonglong2 uA = *(const ulonglong2*)&s_u[k * PXT + px];      // px 0..3
        ulonglong2 uB = *(const ulonglong2*)&s_u[k * PXT + px + 4];  // px 4..7
        float4 wv = *(const float4*)&s_w[k * CC + o0];
        u64 w0 = dup2(wv.x), w1 = dup2(wv.y), w2 = dup2(wv.z), w3 = dup2(wv.w);
        ffma2(acc[0][0], uA.x, w0); ffma2(acc[0][1], uA.y, w0);
        ffma2(acc[0][2], uB.x, w0); ffma2(acc[0][3], uB.y, w0);
        ffma2(acc[1][0], uA.x, w1); ffma2(acc[1][1], uA.y, w1);
        ffma2(acc[1][2], uB.x, w1); ffma2(acc[1][3], uB.y, w1);
        ffma2(acc[2][0], uA.x, w2); ffma2(acc[2][1], uA.y, w2);
        ffma2(acc[2][2], uB.x, w2); ffma2(acc[2][3], uB.y, w2);
        ffma2(acc[3][0], uA.x, w3); ffma2(acc[3][1], uA.y, w3);
        ffma2(acc[3][2], uB.x, w3); ffma2(acc[3][3], uB.y, w3);
    }

    float* op = g_phi + ((size_t)b * CC + o0) * 16384 + pb + px;
#pragma unroll
    for (int j = 0; j < 4; j++)
#pragma unroll
        for (int p = 0; p < 4; p++)
            *(u64*)(op + (size_t)j * 16384 + 2 * p) = acc[j][p];
}

// ---------------------------------------------------------------------------
// K2: M maps (reverted to the measured-faster v1). grid (256 rows, 2 dy-halves),
// block 128 = 4 warps (dy groups). Lane = 4 consecutive pixels. Per channel:
// 1 center LDG.128 + 3 shifted LDG.128 -> 12-float register window serves all
// 7 dx via shifted FMAs.
// ---------------------------------------------------------------------------
__global__ void __launch_bounds__(128)
m_kernel() {
    int lane = threadIdx.x & 31;
    int grp  = (threadIdx.x >> 5) + blockIdx.y * 4;  // 0..6 -> dy = grp-3
    if (grp >= 7) return;                            // idle 4th warp of half 1
    int row  = blockIdx.x;                           // 0..255
    int b = row >> 7, y = row & 127;
    int dy = grp - 3;
    int x  = lane << 2;
    int ys = y + dy;
    bool rowok = (unsigned)ys < (unsigned)HH;
    bool lok = (x > 0);
    bool rok = (x < WW - 4);

    const float* pcb = g_phi + b * CC * 16384 + y  * WW + x;   // +c*16384
    const float* psb = g_phi + b * CC * 16384 + ys * WW + x;

    float acc[28];
#pragma unroll
    for (int i = 0; i < 28; i++) acc[i] = 0.f;

#pragma unroll 4
    for (int c = 0; c < CC; c++) {
        const float* pc_ = pcb + c * 16384;
        const float* ps_ = psb + c * 16384;
        float4 ctr = *(const float4*)pc_;
        float4 w0 = make_float4(0.f, 0.f, 0.f, 0.f);
        float4 w1 = w0, w2 = w0;
        if (rowok) {
            w1 = *(const float4*)ps_;
            if (lok) w0 = *(const float4*)(ps_ - 4);
            if (rok) w2 = *(const float4*)(ps_ + 4);
        }
        float win[12] = {w0.x, w0.y, w0.z, w0.w,
                         w1.x, w1.y, w1.z, w1.w,
                         w2.x, w2.y, w2.z, w2.w};
        float ct[4] = {ctr.x, ctr.y, ctr.z, ctr.w};
#pragma unroll
        for (int d = 0; d < 7; d++)            // dx = d-3
#pragma unroll
            for (int j = 0; j < 4; j++)
                acc[d * 4 + j] += ct[j] * win[1 + d + j];   // phi_s[x+j+(d-3)]
    }

    float* mb = g_M + b * 16384 + y * WW + x;
#pragma unroll
    for (int d = 0; d < 7; d++)
        *(float4*)(mb + (size_t)(grp * 7 + d) * 32768) =
            make_float4(acc[d * 4], acc[d * 4 + 1], acc[d * 4 + 2], acc[d * 4 + 3]);
}

// ---------------------------------------------------------------------------
// K3: boxsum + mask + softmax. grid (2 xb, 128 y, 2 b), block 512.
// Thread (px 0..63, dyg 0..7; dyg==7 idle in compute). Lanes = consecutive x
// -> coalesced M reads. Cross-dy softmax via tiny smem reduction (pitch 9).
// ---------------------------------------------------------------------------
__global__ void __launch_bounds__(512)
attn_kernel(float* __restrict__ out) {
    __shared__ float s_red[64 * 9];
    int t   = threadIdx.x;
    int px  = t & 63;
    int dyg = t >> 6;                          // 0..7
    int b = blockIdx.z, y = blockIdx.y, x = blockIdx.x * 64 + px;

    float sc[7];
    float lmax = -1e30f;
    if (dyg < 7) {
        int dy = dyg - 3;
#pragma unroll
        for (int d3 = 0; d3 < 7; d3++) {
            int dx = d3 - 3;
            float s = 0.f;
            const float* mb = g_M + (size_t)(dyg * 7 + d3) * 32768 + b * 16384;
#pragma unroll
            for (int ey = -1; ey <= 1; ey++) {
                int yy = y + ey;
                if ((unsigned)yy < (unsigned)HH) {
#pragma unroll
                    for (int ex = -1; ex <= 1; ex++) {
                        int xx = x + ex;
                        if ((unsigned)xx < (unsigned)WW) s += mb[yy * WW + xx];
                    }
                }
            }
            bool valid = ((unsigned)(y + dy) < (unsigned)HH) &&
                         ((unsigned)(x + dx) < (unsigned)WW);
            sc[d3] = valid ? s : 0.f;
            lmax = fmaxf(lmax, sc[d3]);
        }
    }
    s_red[px * 9 + dyg] = lmax;                // dyg==7 writes -1e30 (ignored)
    __syncthreads();

    float gmax = s_red[px * 9 + 0];
#pragma unroll
    for (int j = 1; j < 7; j++) gmax = fmaxf(gmax, s_red[px * 9 + j]);

    float e[7];
    float lsum = 0.f;
    if (dyg < 7) {
#pragma unroll
        for (int d3 = 0; d3 < 7; d3++) { e[d3] = __expf(sc[d3] - gmax); lsum += e[d3]; }
    }
    __syncthreads();                           // protect s_red before overwrite
    s_red[px * 9 + dyg] = lsum;                // dyg==7 writes 0 (lsum init, not read)
    __syncthreads();

    float gsum = 0.f;
#pragma unroll
    for (int j = 0; j < 7; j++) gsum += s_red[px * 9 + j];

    if (dyg < 7) {
        float inv = 1.0f / gsum;
        float* op = out + (size_t)(b * 16384 + y * WW + x) * 49 + dyg * 7;
#pragma unroll
        for (int d3 = 0; d3 < 7; d3++) op[d3] = e[d3] * inv;
    }
}

extern "C" void kernel_launch(void* const* d_in, const int* in_sizes, int n_in,
                              void* d_out, int out_size) {
    const float* u = (const float*)d_in[0];    // [2,64,128,128]
    const float* w = (const float*)d_in[1];    // [64,64]
    float* out = (float*)d_out;                // [2,128,128,1,49]

    phi_kernel<<<256, 256>>>(u, w);
    m_kernel<<<dim3(256, 2), 128>>>();
    attn_kernel<<<dim3(2, 128, 2), 512>>>(out);
}

// round 15
// speedup vs baseline: 1.7839x; 1.2038x over previous
#include <cuda_runtime.h>

// SpatialWeightsEsDot on GB300.
//   phi = w_phi @ u (1x1 conv), layout [b][c][y][x]
//   M_{dy,dx}[b][y][x] = sum_c phi[b,c,y,x]*phi[b,c,y+dy,x+dx]  (zero outside image)
//   score[p,d] = 1[p+d in image] * sum_{e in 3x3} M_d[p+e]
//   out = softmax over the 49 offsets -> [2,128,128,1,49]

#define HH 128
#define WW 128
#define CC 64

__device__ float g_phi[2 * CC * HH * WW];     // [b][c][y][x]
__device__ float g_M[49 * 2 * HH * WW];       // [off][b][y][x], off=(dy+3)*7+(dx+3)

typedef unsigned long long u64;

__device__ __forceinline__ void ffma2(u64& d, u64 a, u64 b) {
    asm("fma.rn.f32x2 %0, %1, %2, %3;" : "=l"(d) : "l"(a), "l"(b), "l"(d));
}
__device__ __forceinline__ u64 dup2(float v) {
    u64 d; asm("mov.b64 %0, {%1, %1};" : "=l"(d) : "f"(v)); return d;
}

// ---------------------------------------------------------------------------
// K1: phi v8. Fix for the 4-design plateau at ~25us: ALL variants had ~2048
// warps (3.5/SMSP) + register pressure that blocked load pipelining.
// Now: thread = 4 px x 4 outs (16 acc regs, ~40 total), warp = 128 contiguous
// px (conflict-free LDS.128) sharing ONE out-group (w load = true broadcast,
// N=1 => 1 cyc). Grid (256 px-tiles, 2 out-halves) x 256 thr = 4096 warps
// = 27.7/SM. Per k: 2 LDS.128 + 4 dup-mov + 8 FFMA2.
// ---------------------------------------------------------------------------
__global__ void __launch_bounds__(256)
phi_kernel(const float* __restrict__ u, const float* __restrict__ w) {
    __shared__ float s_u[CC * 128];            // [k][px] 32KB
    __shared__ float s_w[CC * 32];             // [k][o-in-half] 8KB
    int tid  = threadIdx.x;
    int p0   = blockIdx.x * 128;
    int b    = p0 >> 14;
    int pb   = p0 & 16383;
    int half = blockIdx.y;                     // outputs half*32 .. half*32+31

    for (int i = tid; i < CC * 32; i += 256) {
        int k = i >> 5, o = i & 31;
        s_w[i] = w[(half * 32 + o) * CC + k];
    }
    const float* ub = u + (size_t)b * CC * 16384 + pb;
    for (int i = tid; i < 2048; i += 256) {    // 64k x 32 float4
        int k = i >> 5, p4 = (i & 31) << 2;
        *(float4*)&s_u[k * 128 + p4] = *(const float4*)(ub + (size_t)k * 16384 + p4);
    }
    __syncthreads();

    int lane = tid & 31;
    int og   = tid >> 5;                       // warp id 0..7 -> 4 outs
    int px   = lane << 2;                      // 4 contiguous px per lane
    int o0   = og << 2;

    u64 acc[4][2];
#pragma unroll
    for (int j = 0; j < 4; j++) { acc[j][0] = 0ull; acc[j][1] = 0ull; }

#pragma unroll 4
    for (int k = 0; k < CC; k++) {
        ulonglong2 uv = *(const ulonglong2*)&s_u[k * 128 + px];   // px 0..3
        float4 wv = *(const float4*)&s_w[k * 32 + o0];            // broadcast
        u64 w0 = dup2(wv.x), w1 = dup2(wv.y), w2 = dup2(wv.z), w3 = dup2(wv.w);
        ffma2(acc[0][0], uv.x, w0); ffma2(acc[0][1], uv.y, w0);
        ffma2(acc[1][0], uv.x, w1); ffma2(acc[1][1], uv.y, w1);
        ffma2(acc[2][0], uv.x, w2); ffma2(acc[2][1], uv.y, w2);
        ffma2(acc[3][0], uv.x, w3); ffma2(acc[3][1], uv.y, w3);
    }

    float* op = g_phi + ((size_t)b * CC + half * 32 + o0) * 16384 + pb + px;
#pragma unroll
    for (int j = 0; j < 4; j++)
        *(ulonglong2*)(op + (size_t)j * 16384) = make_ulonglong2(acc[j][0], acc[j][1]);
}

// ---------------------------------------------------------------------------
// K2: M maps v3 = v1 + channel split (2x warps for latency hiding).
// grid (256 rows, 2 dy-halves), block 256 = 8 warps: warp w -> dy-group
// (w>>1)+half*4, channel half (w&1)*32. Partial sums combined via pitch-29
// (conflict-free) smem buffer; even warp of each pair stores to g_M.
// ---------------------------------------------------------------------------
__global__ void __launch_bounds__(256)
m_kernel() {
    __shared__ float s_part[4 * 32 * 29];      // [pair][lane][28+pad] 14.5KB
    int tid  = threadIdx.x;
    int lane = tid & 31;
    int wrp  = tid >> 5;                       // 0..7
    int grp  = (wrp >> 1) + blockIdx.y * 4;    // 0..7; 7 = idle
    int chalf= wrp & 1;                        // channels chalf*32..+31
    int pair = wrp >> 1;                       // 0..3
    int row  = blockIdx.x;                     // 0..255
    int b = row >> 7, y = row & 127;
    int dy = grp - 3;
    int x  = lane << 2;
    int ys = y + dy;
    bool live  = (grp < 7);
    bool rowok = live && ((unsigned)ys < (unsigned)HH);
    bool lok = (x > 0);
    bool rok = (x < WW - 4);

    float acc[28];
#pragma unroll
    for (int i = 0; i < 28; i++) acc[i] = 0.f;

    if (live) {
        const float* pcb = g_phi + (size_t)(b * CC + chalf * 32) * 16384 + y  * WW + x;
        const float* psb = g_phi + (size_t)(b * CC + chalf * 32) * 16384 + ys * WW + x;
#pragma unroll 4
        for (int c = 0; c < 32; c++) {
            const float* pc_ = pcb + (size_t)c * 16384;
            const float* ps_ = psb + (size_t)c * 16384;
            float4 ctr = *(const float4*)pc_;
            float4 w0 = make_float4(0.f, 0.f, 0.f, 0.f);
            float4 w1 = w0, w2 = w0;
            if (rowok) {
                w1 = *(const float4*)ps_;
                if (lok) w0 = *(const float4*)(ps_ - 4);
                if (rok) w2 = *(const float4*)(ps_ + 4);
            }
            float win[12] = {w0.x, w0.y, w0.z, w0.w,
                             w1.x, w1.y, w1.z, w1.w,
                             w2.x, w2.y, w2.z, w2.w};
            float ct[4] = {ctr.x, ctr.y, ctr.z, ctr.w};
#pragma unroll
            for (int d = 0; d < 7; d++)        // dx = d-3
#pragma unroll
                for (int j = 0; j < 4; j++)
                    acc[d * 4 + j] += ct[j] * win[1 + d + j];
        }
    }

    // combine the two channel-halves
    if (live && chalf == 1) {
        float* sp = &s_part[(pair * 32 + lane) * 29];
#pragma unroll
        for (int i = 0; i < 28; i++) sp[i] = acc[i];
    }
    __syncthreads();
    if (live && chalf == 0) {
        const float* sp = &s_part[(pair * 32 + lane) * 29];
#pragma unroll
        for (int i = 0; i < 28; i++) acc[i] += sp[i];

        float* mb = g_M + b * 16384 + y * WW + x;
#pragma unroll
        for (int d = 0; d < 7; d++)
            *(float4*)(mb + (size_t)(grp * 7 + d) * 32768) =
                make_float4(acc[d * 4], acc[d * 4 + 1], acc[d * 4 + 2], acc[d * 4 + 3]);
    }
}

// ---------------------------------------------------------------------------
// K3: boxsum + mask + softmax. grid (2 xb, 128 y, 2 b), block 512.
// Thread (px 0..63, dyg 0..7; dyg==7 idle in compute). Lanes = consecutive x
// -> coalesced M reads. Cross-dy softmax via tiny smem reduction (pitch 9).
// ---------------------------------------------------------------------------
__global__ void __launch_bounds__(512)
attn_kernel(float* __restrict__ out) {
    __shared__ float s_red[64 * 9];
    int t   = threadIdx.x;
    int px  = t & 63;
    int dyg = t >> 6;                          // 0..7
    int b = blockIdx.z, y = blockIdx.y, x = blockIdx.x * 64 + px;

    float sc[7];
    float lmax = -1e30f;
    if (dyg < 7) {
        int dy = dyg - 3;
#pragma unroll
        for (int d3 = 0; d3 < 7; d3++) {
            int dx = d3 - 3;
            float s = 0.f;
            const float* mb = g_M + (size_t)(dyg * 7 + d3) * 32768 + b * 16384;
#pragma unroll
            for (int ey = -1; ey <= 1; ey++) {
                int yy = y + ey;
                if ((unsigned)yy < (unsigned)HH) {
#pragma unroll
                    for (int ex = -1; ex <= 1; ex++) {
                        int xx = x + ex;
                        if ((unsigned)xx < (unsigned)WW) s += mb[yy * WW + xx];
                    }
                }
            }
            bool valid = ((unsigned)(y + dy) < (unsigned)HH) &&
                         ((unsigned)(x + dx) < (unsigned)WW);
            sc[d3] = valid ? s : 0.f;
            lmax = fmaxf(lmax, sc[d3]);
        }
    }
    s_red[px * 9 + dyg] = lmax;                // dyg==7 writes -1e30 (ignored)
    __syncthreads();

    float gmax = s_red[px * 9 + 0];
#pragma unroll
    for (int j = 1; j < 7; j++) gmax = fmaxf(gmax, s_red[px * 9 + j]);

    float e[7];
    float lsum = 0.f;
    if (dyg < 7) {
#pragma unroll
        for (int d3 = 0; d3 < 7; d3++) { e[d3] = __expf(sc[d3] - gmax); lsum += e[d3]; }
    }
    __syncthreads();                           // protect s_red before overwrite
    s_red[px * 9 + dyg] = lsum;                // dyg==7 writes 0 (lsum init, not read)
    __syncthreads();

    float gsum = 0.f;
#pragma unroll
    for (int j = 0; j < 7; j++) gsum += s_red[px * 9 + j];

    if (dyg < 7) {
        float inv = 1.0f / gsum;
        float* op = out + (size_t)(b * 16384 + y * WW + x) * 49 + dyg * 7;
#pragma unroll
        for (int d3 = 0; d3 < 7; d3++) op[d3] = e[d3] * inv;
    }
}

extern "C" void kernel_launch(void* const* d_in, const int* in_sizes, int n_in,
                              void* d_out, int out_size) {
    const float* u = (const float*)d_in[0];    // [2,64,128,128]
    const float* w = (const float*)d_in[1];    // [64,64]
    float* out = (float*)d_out;                // [2,128,128,1,49]

    phi_kernel<<<dim3(256, 2), 256>>>(u, w);
    m_kernel<<<dim3(256, 2), 256>>>();
    attn_kernel<<<dim3(2, 128, 2), 512>>>(out);
}